// round 9
// baseline (speedup 1.0000x reference)
#include <cuda_runtime.h>
#include <cstdint>

#define N_NODES 100000
#define MAX_EDGES 1700000
#define D 128
#define SC_T 1024

// ---------------- scratch ----------------
__device__ float4 g_g4[(size_t)N_NODES * (D / 4)];   // g = dinv * (x @ W^T)
__device__ int    g_deg[N_NODES];                    // in-degree per dst (edges only)
__device__ int    g_off[N_NODES];                    // CSR exclusive offsets
__device__ int    g_cur[N_NODES];                    // scatter cursors
__device__ int    g_csr[MAX_EDGES];                  // src index per CSR slot

// ---------------- helpers ----------------
// Per-block int64-vs-int32 detect: int64 indices < 2^31 have all-zero odd
// 32-bit words; int32 indices are random nonzero. Checks 64 words.
__device__ __forceinline__ int block_detect_is64(const int* ei32) {
    int nz = 0;
    if (threadIdx.x < 64) nz = (ei32[2 * threadIdx.x + 1] != 0);
    return !__syncthreads_or(nz);
}

__device__ __forceinline__ unsigned long long pack_dup(float a) {
    unsigned long long r;
    unsigned int u = __float_as_uint(a);
    asm("mov.b64 %0, {%1, %2};" : "=l"(r) : "r"(u), "r"(u));
    return r;
}
__device__ __forceinline__ void fma2(unsigned long long& c,
                                     unsigned long long a,
                                     unsigned long long b) {
    asm("fma.rn.f32x2 %0, %1, %2, %3;" : "=l"(c) : "l"(a), "l"(b), "l"(c));
}
__device__ __forceinline__ void mul2(unsigned long long& c,
                                     unsigned long long a) {
    asm("mul.rn.f32x2 %0, %1, %0;" : "+l"(c) : "l"(a));
}

// ---------------- kernels ----------------
__global__ void zero_deg_kernel(int n) {
    int i = blockIdx.x * blockDim.x + threadIdx.x;
    if (i < n) g_deg[i] = 0;
}

__global__ void deg_kernel(const void* __restrict__ ei, int E) {
    int is64 = block_detect_is64((const int*)ei);
    int i = blockIdx.x * blockDim.x + threadIdx.x;
    if (i >= E) return;
    int d;
    if (is64) d = (int)((const long long*)ei)[(size_t)E + i];
    else      d = ((const int*)ei)[(size_t)E + i];
    if ((unsigned)d < (unsigned)N_NODES) atomicAdd(&g_deg[d], 1);
}

// Single-block exclusive scan of g_deg -> g_off (+ cursor copy).
__global__ __launch_bounds__(SC_T) void scan_kernel(int n) {
    __shared__ int sh[SC_T];
    int t = threadIdx.x;
    int chunk = (n + SC_T - 1) / SC_T;
    int lo = t * chunk;
    int hi = lo + chunk; if (hi > n) hi = n;

    int sum = 0;
    for (int i = lo; i < hi; i++) sum += g_deg[i];
    sh[t] = sum;
    __syncthreads();
#pragma unroll
    for (int o = 1; o < SC_T; o <<= 1) {
        int add = (t >= o) ? sh[t - o] : 0;
        __syncthreads();
        sh[t] += add;
        __syncthreads();
    }
    int run = sh[t] - sum;          // exclusive base for this chunk
    for (int i = lo; i < hi; i++) {
        g_off[i] = run;
        g_cur[i] = run;
        run += g_deg[i];
    }
}

__global__ void csr_kernel(const void* __restrict__ ei, int E) {
    int is64 = block_detect_is64((const int*)ei);
    int i = blockIdx.x * blockDim.x + threadIdx.x;
    if (i >= E) return;
    int s, d;
    if (is64) {
        const long long* p = (const long long*)ei;
        s = (int)p[i];
        d = (int)p[(size_t)E + i];
    } else {
        const int* p = (const int*)ei;
        s = p[i];
        d = p[(size_t)E + i];
    }
    if ((unsigned)s >= (unsigned)N_NODES || (unsigned)d >= (unsigned)N_NODES) return;
    int pos = atomicAdd(&g_cur[d], 1);
    g_csr[pos] = s;
}

// ---------------- SGEMM: g = dinv * (x @ W^T), packed f32x2 FMA ----------------
#define BM 128
#define KT 32
__global__ __launch_bounds__(256) void gemm_scale_kernel(
    const float* __restrict__ x, const float* __restrict__ W, int N)
{
    __shared__ float xs[KT][BM + 4];   // [k][m]
    __shared__ float ws[KT][D + 4];    // [k][n] (W loaded transposed on the fly)

    const int tid = threadIdx.x;
    const int tx = tid & 15;
    const int ty = tid >> 4;
    const int m0 = ty * 8;
    const int n0 = tx * 8;
    const int rowBase = blockIdx.x * BM;

    unsigned long long c2[8][4];       // 8 rows x 4 col-pairs (cols n0..n0+7)
#pragma unroll
    for (int i = 0; i < 8; i++)
#pragma unroll
        for (int j = 0; j < 4; j++) c2[i][j] = 0ull;

    for (int kt = 0; kt < D; kt += KT) {
        // x tile: thread loads float4 along k, stores k-major
#pragma unroll
        for (int it = 0; it < 4; it++) {
            int i = tid + it * 256;            // 0..1023 float4 slots
            int m = i >> 3;
            int kq = i & 7;
            float4 v = make_float4(0.f, 0.f, 0.f, 0.f);
            int row = rowBase + m;
            if (row < N)
                v = *(const float4*)(x + (size_t)row * D + kt + kq * 4);
            xs[kq * 4 + 0][m] = v.x;
            xs[kq * 4 + 1][m] = v.y;
            xs[kq * 4 + 2][m] = v.z;
            xs[kq * 4 + 3][m] = v.w;
        }
        // W tile: W[n][k] -> ws[k][n] (transpose during smem store)
#pragma unroll
        for (int it = 0; it < 4; it++) {
            int i = tid + it * 256;
            int n = i >> 3;
            int kq = i & 7;
            float4 v = *(const float4*)(W + (size_t)n * D + kt + kq * 4);
            ws[kq * 4 + 0][n] = v.x;
            ws[kq * 4 + 1][n] = v.y;
            ws[kq * 4 + 2][n] = v.z;
            ws[kq * 4 + 3][n] = v.w;
        }
        __syncthreads();

#pragma unroll
        for (int k = 0; k < KT; k++) {
            float4 a0 = *(const float4*)&xs[k][m0];
            float4 a1 = *(const float4*)&xs[k][m0 + 4];
            ulonglong2 B0 = *(const ulonglong2*)&ws[k][n0];      // cols n0..n0+3
            ulonglong2 B1 = *(const ulonglong2*)&ws[k][n0 + 4];  // cols n0+4..n0+7
            unsigned long long b[4] = {B0.x, B0.y, B1.x, B1.y};
            float a[8] = {a0.x, a0.y, a0.z, a0.w, a1.x, a1.y, a1.z, a1.w};
#pragma unroll
            for (int i = 0; i < 8; i++) {
                unsigned long long ad = pack_dup(a[i]);
#pragma unroll
                for (int j = 0; j < 4; j++)
                    fma2(c2[i][j], ad, b[j]);
            }
        }
        __syncthreads();
    }

#pragma unroll
    for (int i = 0; i < 8; i++) {
        int row = rowBase + m0 + i;
        if (row >= N) continue;
        float dinv = rsqrtf((float)g_deg[row] + 1.0f);
        unsigned long long dv = pack_dup(dinv);
#pragma unroll
        for (int j = 0; j < 4; j++) mul2(c2[i][j], dv);
        size_t base = (size_t)row * (D / 4) + (n0 >> 2);
        ulonglong2 o0, o1;
        o0.x = c2[i][0]; o0.y = c2[i][1];
        o1.x = c2[i][2]; o1.y = c2[i][3];
        *(ulonglong2*)&g_g4[base]     = o0;
        *(ulonglong2*)&g_g4[base + 1] = o1;
    }
}

// ---------------- aggregate + epilogue: warp per node, MLP=8 ----------------
__global__ __launch_bounds__(256) void agg_kernel(
    const float* __restrict__ b, float* __restrict__ out, int N)
{
    int w = (blockIdx.x * blockDim.x + threadIdx.x) >> 5;
    int lane = threadIdx.x & 31;
    if (w >= N) return;

    int deg = g_deg[w];
    int e = g_off[w];
    float dinv = rsqrtf((float)deg + 1.0f);

    float4 acc = g_g4[(size_t)w * 32 + lane];   // self loop

    int cnt = deg;
    while (cnt >= 8) {
        int s[8];
#pragma unroll
        for (int u = 0; u < 8; u++) s[u] = __ldg(&g_csr[e + u]);
        float4 v[8];
#pragma unroll
        for (int u = 0; u < 8; u++) v[u] = g_g4[(size_t)s[u] * 32 + lane];
        acc.x += ((v[0].x + v[1].x) + (v[2].x + v[3].x)) +
                 ((v[4].x + v[5].x) + (v[6].x + v[7].x));
        acc.y += ((v[0].y + v[1].y) + (v[2].y + v[3].y)) +
                 ((v[4].y + v[5].y) + (v[6].y + v[7].y));
        acc.z += ((v[0].z + v[1].z) + (v[2].z + v[3].z)) +
                 ((v[4].z + v[5].z) + (v[6].z + v[7].z));
        acc.w += ((v[0].w + v[1].w) + (v[2].w + v[3].w)) +
                 ((v[4].w + v[5].w) + (v[6].w + v[7].w));
        e += 8; cnt -= 8;
    }
    if (cnt >= 4) {
        int s0 = __ldg(&g_csr[e + 0]);
        int s1 = __ldg(&g_csr[e + 1]);
        int s2 = __ldg(&g_csr[e + 2]);
        int s3 = __ldg(&g_csr[e + 3]);
        float4 v0 = g_g4[(size_t)s0 * 32 + lane];
        float4 v1 = g_g4[(size_t)s1 * 32 + lane];
        float4 v2 = g_g4[(size_t)s2 * 32 + lane];
        float4 v3 = g_g4[(size_t)s3 * 32 + lane];
        acc.x += (v0.x + v1.x) + (v2.x + v3.x);
        acc.y += (v0.y + v1.y) + (v2.y + v3.y);
        acc.z += (v0.z + v1.z) + (v2.z + v3.z);
        acc.w += (v0.w + v1.w) + (v2.w + v3.w);
        e += 4; cnt -= 4;
    }
    while (cnt > 0) {
        int s = __ldg(&g_csr[e]);
        float4 v = g_g4[(size_t)s * 32 + lane];
        acc.x += v.x; acc.y += v.y; acc.z += v.z; acc.w += v.w;
        e++; cnt--;
    }

    float4 bb = *(const float4*)(b + lane * 4);
    float4 o;
    o.x = fmaxf(fmaf(acc.x, dinv, bb.x), 0.0f);
    o.y = fmaxf(fmaf(acc.y, dinv, bb.y), 0.0f);
    o.z = fmaxf(fmaf(acc.z, dinv, bb.z), 0.0f);
    o.w = fmaxf(fmaf(acc.w, dinv, bb.w), 0.0f);
    *(float4*)(out + (size_t)w * D + lane * 4) = o;
}

// ---------------- launch ----------------
extern "C" void kernel_launch(void* const* d_in, const int* in_sizes, int n_in,
                              void* d_out, int out_size)
{
    const float* x  = (const float*)d_in[0];
    const void*  ei = d_in[1];                 // [2, E], int64 OR int32 (detected)
    const float* W  = (const float*)d_in[2];
    const float* b  = (const float*)d_in[3];
    float* out = (float*)d_out;

    const int N = in_sizes[0] / D;
    const int E = in_sizes[1] / 2;

    zero_deg_kernel<<<(N + 255) / 256, 256>>>(N);
    deg_kernel<<<(E + 255) / 256, 256>>>(ei, E);
    scan_kernel<<<1, SC_T>>>(N);
    csr_kernel<<<(E + 255) / 256, 256>>>(ei, E);
    gemm_scale_kernel<<<(N + BM - 1) / BM, 256>>>(x, W, N);
    agg_kernel<<<(N * 32 + 255) / 256, 256>>>(b, out, N);
}

// round 10
// speedup vs baseline: 1.8920x; 1.8920x over previous
#include <cuda_runtime.h>
#include <cstdint>

#define N_NODES 100000
#define MAX_EDGES 1700000
#define D 128
#define SCAN_BLK 1024

// ---------------- scratch ----------------
__device__ float4 g_g4[(size_t)N_NODES * (D / 4)];   // g = dinv * (x @ W^T)
__device__ int    g_deg[N_NODES];                    // in-degree per dst (edges only)
__device__ int    g_off[N_NODES];                    // CSR exclusive offsets
__device__ int    g_cur[N_NODES];                    // scatter cursors
__device__ int    g_csr[MAX_EDGES];                  // src index per CSR slot
__device__ int    g_bsum[128];                       // per-block scan sums
__device__ int    g_boff[128];                       // per-block scan offsets

// ---------------- helpers ----------------
// Per-block int64-vs-int32 detect: int64 indices < 2^31 have all-zero odd
// 32-bit words; int32 indices are effectively-random nonzero. Checks 64 words.
__device__ __forceinline__ int block_detect_is64(const int* ei32) {
    int nz = 0;
    if (threadIdx.x < 64) nz = (ei32[2 * threadIdx.x + 1] != 0);
    return !__syncthreads_or(nz);
}

// ---------------- kernels ----------------
__global__ void zero_deg_kernel(int n) {
    int i = blockIdx.x * blockDim.x + threadIdx.x;
    if (i < n) g_deg[i] = 0;
}

__global__ void deg_kernel(const void* __restrict__ ei, int E) {
    int is64 = block_detect_is64((const int*)ei);
    int i = blockIdx.x * blockDim.x + threadIdx.x;
    if (i >= E) return;
    int d;
    if (is64) d = (int)((const long long*)ei)[(size_t)E + i];
    else      d = ((const int*)ei)[(size_t)E + i];
    if ((unsigned)d < (unsigned)N_NODES) atomicAdd(&g_deg[d], 1);
}

// ---------------- exclusive scan of g_deg -> g_off (3 kernels, coalesced) ----
__global__ void scan1_kernel(int n) {
    __shared__ int sh[SCAN_BLK];
    int t = threadIdx.x;
    int i = blockIdx.x * SCAN_BLK + t;
    int v = (i < n) ? g_deg[i] : 0;
    sh[t] = v;
    __syncthreads();
#pragma unroll
    for (int o = 1; o < SCAN_BLK; o <<= 1) {
        int add = (t >= o) ? sh[t - o] : 0;
        __syncthreads();
        sh[t] += add;
        __syncthreads();
    }
    if (i < n) g_off[i] = sh[t] - v;          // exclusive
    if (t == SCAN_BLK - 1) g_bsum[blockIdx.x] = sh[t];
}

__global__ void scan2_kernel(int nb) {
    __shared__ int sh[128];
    int t = threadIdx.x;
    int v = (t < nb) ? g_bsum[t] : 0;
    sh[t] = v;
    __syncthreads();
#pragma unroll
    for (int o = 1; o < 128; o <<= 1) {
        int add = (t >= o) ? sh[t - o] : 0;
        __syncthreads();
        sh[t] += add;
        __syncthreads();
    }
    if (t < nb) g_boff[t] = sh[t] - v;        // exclusive
}

__global__ void scan3_kernel(int n) {
    int i = blockIdx.x * SCAN_BLK + threadIdx.x;
    if (i < n) {
        int o = g_off[i] + g_boff[blockIdx.x];
        g_off[i] = o;
        g_cur[i] = o;
    }
}

// ---------------- scatter edges into CSR (by dst) ----------------
__global__ void csr_kernel(const void* __restrict__ ei, int E) {
    int is64 = block_detect_is64((const int*)ei);
    int i = blockIdx.x * blockDim.x + threadIdx.x;
    if (i >= E) return;
    int s, d;
    if (is64) {
        const long long* p = (const long long*)ei;
        s = (int)p[i];
        d = (int)p[(size_t)E + i];
    } else {
        const int* p = (const int*)ei;
        s = p[i];
        d = p[(size_t)E + i];
    }
    if ((unsigned)s >= (unsigned)N_NODES || (unsigned)d >= (unsigned)N_NODES) return;
    int pos = atomicAdd(&g_cur[d], 1);
    g_csr[pos] = s;
}

// ---------------- SGEMM: g = dinv * (x @ W^T) ----------------
// Round-7 measured-good version: k-major smem, LDS.128 inner loop, plain FFMA.
// W loaded transposed directly from global (transpose kernel eliminated).
#define BM 128
#define KT 32
__global__ __launch_bounds__(256) void gemm_scale_kernel(
    const float* __restrict__ x, const float* __restrict__ W, int N)
{
    __shared__ float xs[KT][BM + 4];   // [k][m]
    __shared__ float ws[KT][D + 4];    // [k][n]

    const int tid = threadIdx.x;
    const int tx = tid & 15;
    const int ty = tid >> 4;
    const int m0 = ty * 8;
    const int n0 = tx * 8;
    const int rowBase = blockIdx.x * BM;

    float c[8][8];
#pragma unroll
    for (int i = 0; i < 8; i++)
#pragma unroll
        for (int j = 0; j < 8; j++) c[i][j] = 0.0f;

    for (int kt = 0; kt < D; kt += KT) {
        // x tile: load float4 along k (coalesced), store k-major
#pragma unroll
        for (int it = 0; it < 4; it++) {
            int i = tid + it * 256;            // 0..1023 float4 slots
            int m = i >> 3;
            int kq = i & 7;
            float4 v = make_float4(0.f, 0.f, 0.f, 0.f);
            int row = rowBase + m;
            if (row < N)
                v = *(const float4*)(x + (size_t)row * D + kt + kq * 4);
            xs[kq * 4 + 0][m] = v.x;
            xs[kq * 4 + 1][m] = v.y;
            xs[kq * 4 + 2][m] = v.z;
            xs[kq * 4 + 3][m] = v.w;
        }
        // W tile: W[n][k] (coalesced float4 along k) -> ws[k][n]
#pragma unroll
        for (int it = 0; it < 4; it++) {
            int i = tid + it * 256;
            int n = i >> 3;
            int kq = i & 7;
            float4 v = *(const float4*)(W + (size_t)n * D + kt + kq * 4);
            ws[kq * 4 + 0][n] = v.x;
            ws[kq * 4 + 1][n] = v.y;
            ws[kq * 4 + 2][n] = v.z;
            ws[kq * 4 + 3][n] = v.w;
        }
        __syncthreads();

#pragma unroll
        for (int k = 0; k < KT; k++) {
            float4 a0 = *(const float4*)&xs[k][m0];
            float4 a1 = *(const float4*)&xs[k][m0 + 4];
            float4 b0 = *(const float4*)&ws[k][n0];
            float4 b1 = *(const float4*)&ws[k][n0 + 4];
            float a[8] = {a0.x, a0.y, a0.z, a0.w, a1.x, a1.y, a1.z, a1.w};
            float b[8] = {b0.x, b0.y, b0.z, b0.w, b1.x, b1.y, b1.z, b1.w};
#pragma unroll
            for (int i = 0; i < 8; i++)
#pragma unroll
                for (int j = 0; j < 8; j++)
                    c[i][j] = fmaf(a[i], b[j], c[i][j]);
        }
        __syncthreads();
    }

#pragma unroll
    for (int i = 0; i < 8; i++) {
        int row = rowBase + m0 + i;
        if (row >= N) continue;
        float dinv = rsqrtf((float)g_deg[row] + 1.0f);
        size_t base = (size_t)row * (D / 4) + (n0 >> 2);
        float4 v0, v1;
        v0.x = c[i][0] * dinv; v0.y = c[i][1] * dinv;
        v0.z = c[i][2] * dinv; v0.w = c[i][3] * dinv;
        v1.x = c[i][4] * dinv; v1.y = c[i][5] * dinv;
        v1.z = c[i][6] * dinv; v1.w = c[i][7] * dinv;
        g_g4[base]     = v0;
        g_g4[base + 1] = v1;
    }
}

// ---------------- aggregate + epilogue: warp per node, MLP=8 ----------------
__global__ __launch_bounds__(256) void agg_kernel(
    const float* __restrict__ b, float* __restrict__ out, int N)
{
    int w = (blockIdx.x * blockDim.x + threadIdx.x) >> 5;
    int lane = threadIdx.x & 31;
    if (w >= N) return;

    int deg = g_deg[w];
    int e = g_off[w];
    float dinv = rsqrtf((float)deg + 1.0f);

    float4 acc = g_g4[(size_t)w * 32 + lane];   // self loop

    int cnt = deg;
    while (cnt >= 8) {
        int s[8];
#pragma unroll
        for (int u = 0; u < 8; u++) s[u] = __ldg(&g_csr[e + u]);
        float4 v[8];
#pragma unroll
        for (int u = 0; u < 8; u++) v[u] = g_g4[(size_t)s[u] * 32 + lane];
        acc.x += ((v[0].x + v[1].x) + (v[2].x + v[3].x)) +
                 ((v[4].x + v[5].x) + (v[6].x + v[7].x));
        acc.y += ((v[0].y + v[1].y) + (v[2].y + v[3].y)) +
                 ((v[4].y + v[5].y) + (v[6].y + v[7].y));
        acc.z += ((v[0].z + v[1].z) + (v[2].z + v[3].z)) +
                 ((v[4].z + v[5].z) + (v[6].z + v[7].z));
        acc.w += ((v[0].w + v[1].w) + (v[2].w + v[3].w)) +
                 ((v[4].w + v[5].w) + (v[6].w + v[7].w));
        e += 8; cnt -= 8;
    }
    if (cnt >= 4) {
        int s0 = __ldg(&g_csr[e + 0]);
        int s1 = __ldg(&g_csr[e + 1]);
        int s2 = __ldg(&g_csr[e + 2]);
        int s3 = __ldg(&g_csr[e + 3]);
        float4 v0 = g_g4[(size_t)s0 * 32 + lane];
        float4 v1 = g_g4[(size_t)s1 * 32 + lane];
        float4 v2 = g_g4[(size_t)s2 * 32 + lane];
        float4 v3 = g_g4[(size_t)s3 * 32 + lane];
        acc.x += (v0.x + v1.x) + (v2.x + v3.x);
        acc.y += (v0.y + v1.y) + (v2.y + v3.y);
        acc.z += (v0.z + v1.z) + (v2.z + v3.z);
        acc.w += (v0.w + v1.w) + (v2.w + v3.w);
        e += 4; cnt -= 4;
    }
    while (cnt > 0) {
        int s = __ldg(&g_csr[e]);
        float4 v = g_g4[(size_t)s * 32 + lane];
        acc.x += v.x; acc.y += v.y; acc.z += v.z; acc.w += v.w;
        e++; cnt--;
    }

    float4 bb = *(const float4*)(b + lane * 4);
    float4 o;
    o.x = fmaxf(fmaf(acc.x, dinv, bb.x), 0.0f);
    o.y = fmaxf(fmaf(acc.y, dinv, bb.y), 0.0f);
    o.z = fmaxf(fmaf(acc.z, dinv, bb.z), 0.0f);
    o.w = fmaxf(fmaf(acc.w, dinv, bb.w), 0.0f);
    *(float4*)(out + (size_t)w * D + lane * 4) = o;
}

// ---------------- launch ----------------
extern "C" void kernel_launch(void* const* d_in, const int* in_sizes, int n_in,
                              void* d_out, int out_size)
{
    const float* x  = (const float*)d_in[0];
    const void*  ei = d_in[1];                 // [2, E], int64 OR int32 (detected)
    const float* W  = (const float*)d_in[2];
    const float* b  = (const float*)d_in[3];
    float* out = (float*)d_out;

    const int N = in_sizes[0] / D;
    const int E = in_sizes[1] / 2;
    const int NB = (N + SCAN_BLK - 1) / SCAN_BLK;

    zero_deg_kernel<<<(N + 255) / 256, 256>>>(N);
    deg_kernel<<<(E + 255) / 256, 256>>>(ei, E);
    scan1_kernel<<<NB, SCAN_BLK>>>(N);
    scan2_kernel<<<1, 128>>>(NB);
    scan3_kernel<<<NB, SCAN_BLK>>>(N);
    csr_kernel<<<(E + 255) / 256, 256>>>(ei, E);
    gemm_scale_kernel<<<(N + BM - 1) / BM, 256>>>(x, W, N);
    agg_kernel<<<(N * 32 + 255) / 256, 256>>>(b, out, N);
}

// round 11
// speedup vs baseline: 2.1125x; 1.1165x over previous
#include <cuda_runtime.h>
#include <cuda_fp16.h>
#include <cstdint>

#define N_NODES 100000
#define MAX_EDGES 1700000
#define D 128
#define SCAN_BLK 1024

// ---------------- scratch ----------------
// g stored as fp16: row = 128 halfs = 256B = 32 uint2 (each uint2 = 4 halfs)
__device__ uint2  g_gh[(size_t)N_NODES * 32];
__device__ int    g_deg[N_NODES];                    // in-degree per dst (edges only)
__device__ int    g_off[N_NODES];                    // CSR exclusive offsets
__device__ int    g_cur[N_NODES];                    // scatter cursors
__device__ int    g_csr[MAX_EDGES];                  // src index per CSR slot
__device__ int    g_bsum[128];                       // per-block scan sums
__device__ int    g_boff[128];                       // per-block scan offsets

// ---------------- helpers ----------------
__device__ __forceinline__ int block_detect_is64(const int* ei32) {
    int nz = 0;
    if (threadIdx.x < 64) nz = (ei32[2 * threadIdx.x + 1] != 0);
    return !__syncthreads_or(nz);
}

// ---------------- kernels ----------------
__global__ void zero_deg_kernel(int n) {
    int i = blockIdx.x * blockDim.x + threadIdx.x;
    if (i < n) g_deg[i] = 0;
}

__global__ void deg_kernel(const void* __restrict__ ei, int E) {
    int is64 = block_detect_is64((const int*)ei);
    int i = blockIdx.x * blockDim.x + threadIdx.x;
    if (i >= E) return;
    int d;
    if (is64) d = (int)((const long long*)ei)[(size_t)E + i];
    else      d = ((const int*)ei)[(size_t)E + i];
    if ((unsigned)d < (unsigned)N_NODES) atomicAdd(&g_deg[d], 1);
}

// ---------------- exclusive scan of g_deg -> g_off (3 kernels, coalesced) ----
__global__ void scan1_kernel(int n) {
    __shared__ int sh[SCAN_BLK];
    int t = threadIdx.x;
    int i = blockIdx.x * SCAN_BLK + t;
    int v = (i < n) ? g_deg[i] : 0;
    sh[t] = v;
    __syncthreads();
#pragma unroll
    for (int o = 1; o < SCAN_BLK; o <<= 1) {
        int add = (t >= o) ? sh[t - o] : 0;
        __syncthreads();
        sh[t] += add;
        __syncthreads();
    }
    if (i < n) g_off[i] = sh[t] - v;          // exclusive
    if (t == SCAN_BLK - 1) g_bsum[blockIdx.x] = sh[t];
}

__global__ void scan2_kernel(int nb) {
    __shared__ int sh[128];
    int t = threadIdx.x;
    int v = (t < nb) ? g_bsum[t] : 0;
    sh[t] = v;
    __syncthreads();
#pragma unroll
    for (int o = 1; o < 128; o <<= 1) {
        int add = (t >= o) ? sh[t - o] : 0;
        __syncthreads();
        sh[t] += add;
        __syncthreads();
    }
    if (t < nb) g_boff[t] = sh[t] - v;        // exclusive
}

__global__ void scan3_kernel(int n) {
    int i = blockIdx.x * SCAN_BLK + threadIdx.x;
    if (i < n) {
        int o = g_off[i] + g_boff[blockIdx.x];
        g_off[i] = o;
        g_cur[i] = o;
    }
}

// ---------------- scatter edges into CSR (by dst) ----------------
__global__ void csr_kernel(const void* __restrict__ ei, int E) {
    int is64 = block_detect_is64((const int*)ei);
    int i = blockIdx.x * blockDim.x + threadIdx.x;
    if (i >= E) return;
    int s, d;
    if (is64) {
        const long long* p = (const long long*)ei;
        s = (int)p[i];
        d = (int)p[(size_t)E + i];
    } else {
        const int* p = (const int*)ei;
        s = p[i];
        d = p[(size_t)E + i];
    }
    if ((unsigned)s >= (unsigned)N_NODES || (unsigned)d >= (unsigned)N_NODES) return;
    int pos = atomicAdd(&g_cur[d], 1);
    g_csr[pos] = s;
}

// ---------------- SGEMM: g = fp16( dinv * (x @ W^T) ) ----------------
// Round-7/9 measured-good body; only the epilogue store format changed.
#define BM 128
#define KT 32
__global__ __launch_bounds__(256) void gemm_scale_kernel(
    const float* __restrict__ x, const float* __restrict__ W, int N)
{
    __shared__ float xs[KT][BM + 4];   // [k][m]
    __shared__ float ws[KT][D + 4];    // [k][n]

    const int tid = threadIdx.x;
    const int tx = tid & 15;
    const int ty = tid >> 4;
    const int m0 = ty * 8;
    const int n0 = tx * 8;
    const int rowBase = blockIdx.x * BM;

    float c[8][8];
#pragma unroll
    for (int i = 0; i < 8; i++)
#pragma unroll
        for (int j = 0; j < 8; j++) c[i][j] = 0.0f;

    for (int kt = 0; kt < D; kt += KT) {
#pragma unroll
        for (int it = 0; it < 4; it++) {
            int i = tid + it * 256;            // 0..1023 float4 slots
            int m = i >> 3;
            int kq = i & 7;
            float4 v = make_float4(0.f, 0.f, 0.f, 0.f);
            int row = rowBase + m;
            if (row < N)
                v = *(const float4*)(x + (size_t)row * D + kt + kq * 4);
            xs[kq * 4 + 0][m] = v.x;
            xs[kq * 4 + 1][m] = v.y;
            xs[kq * 4 + 2][m] = v.z;
            xs[kq * 4 + 3][m] = v.w;
        }
#pragma unroll
        for (int it = 0; it < 4; it++) {
            int i = tid + it * 256;
            int n = i >> 3;
            int kq = i & 7;
            float4 v = *(const float4*)(W + (size_t)n * D + kt + kq * 4);
            ws[kq * 4 + 0][n] = v.x;
            ws[kq * 4 + 1][n] = v.y;
            ws[kq * 4 + 2][n] = v.z;
            ws[kq * 4 + 3][n] = v.w;
        }
        __syncthreads();

#pragma unroll
        for (int k = 0; k < KT; k++) {
            float4 a0 = *(const float4*)&xs[k][m0];
            float4 a1 = *(const float4*)&xs[k][m0 + 4];
            float4 b0 = *(const float4*)&ws[k][n0];
            float4 b1 = *(const float4*)&ws[k][n0 + 4];
            float a[8] = {a0.x, a0.y, a0.z, a0.w, a1.x, a1.y, a1.z, a1.w};
            float b[8] = {b0.x, b0.y, b0.z, b0.w, b1.x, b1.y, b1.z, b1.w};
#pragma unroll
            for (int i = 0; i < 8; i++)
#pragma unroll
                for (int j = 0; j < 8; j++)
                    c[i][j] = fmaf(a[i], b[j], c[i][j]);
        }
        __syncthreads();
    }

    // epilogue: g = fp16(dinv * h); 8 cols = 4 half2 = 2 uint2
#pragma unroll
    for (int i = 0; i < 8; i++) {
        int row = rowBase + m0 + i;
        if (row >= N) continue;
        float dinv = rsqrtf((float)g_deg[row] + 1.0f);
        __half2 h0 = __floats2half2_rn(c[i][0] * dinv, c[i][1] * dinv);
        __half2 h1 = __floats2half2_rn(c[i][2] * dinv, c[i][3] * dinv);
        __half2 h2 = __floats2half2_rn(c[i][4] * dinv, c[i][5] * dinv);
        __half2 h3 = __floats2half2_rn(c[i][6] * dinv, c[i][7] * dinv);
        uint2 u0, u1;
        u0.x = *(unsigned int*)&h0; u0.y = *(unsigned int*)&h1;
        u1.x = *(unsigned int*)&h2; u1.y = *(unsigned int*)&h3;
        size_t base = (size_t)row * 32 + (n0 >> 2);   // uint2 granularity (4 halfs)
        g_gh[base]     = u0;
        g_gh[base + 1] = u1;
    }
}

// ---------------- aggregate + epilogue: warp per node, MLP=8, fp16 gather ----
__device__ __forceinline__ void acc_u2(float& a0, float& a1, float& a2, float& a3,
                                       uint2 u) {
    float2 p = __half22float2(*(__half2*)&u.x);
    float2 q = __half22float2(*(__half2*)&u.y);
    a0 += p.x; a1 += p.y; a2 += q.x; a3 += q.y;
}

__global__ __launch_bounds__(256) void agg_kernel(
    const float* __restrict__ b, float* __restrict__ out, int N)
{
    int w = (blockIdx.x * blockDim.x + threadIdx.x) >> 5;
    int lane = threadIdx.x & 31;
    if (w >= N) return;

    int deg = g_deg[w];
    int e = g_off[w];
    float dinv = rsqrtf((float)deg + 1.0f);

    float a0 = 0.f, a1 = 0.f, a2 = 0.f, a3 = 0.f;
    acc_u2(a0, a1, a2, a3, g_gh[(size_t)w * 32 + lane]);   // self loop

    int cnt = deg;
    while (cnt >= 8) {
        int s[8];
#pragma unroll
        for (int u = 0; u < 8; u++) s[u] = __ldg(&g_csr[e + u]);
        uint2 v[8];
#pragma unroll
        for (int u = 0; u < 8; u++) v[u] = g_gh[(size_t)s[u] * 32 + lane];
#pragma unroll
        for (int u = 0; u < 8; u++) acc_u2(a0, a1, a2, a3, v[u]);
        e += 8; cnt -= 8;
    }
    if (cnt >= 4) {
        int s0 = __ldg(&g_csr[e + 0]);
        int s1 = __ldg(&g_csr[e + 1]);
        int s2 = __ldg(&g_csr[e + 2]);
        int s3 = __ldg(&g_csr[e + 3]);
        uint2 v0 = g_gh[(size_t)s0 * 32 + lane];
        uint2 v1 = g_gh[(size_t)s1 * 32 + lane];
        uint2 v2 = g_gh[(size_t)s2 * 32 + lane];
        uint2 v3 = g_gh[(size_t)s3 * 32 + lane];
        acc_u2(a0, a1, a2, a3, v0);
        acc_u2(a0, a1, a2, a3, v1);
        acc_u2(a0, a1, a2, a3, v2);
        acc_u2(a0, a1, a2, a3, v3);
        e += 4; cnt -= 4;
    }
    while (cnt > 0) {
        int s = __ldg(&g_csr[e]);
        acc_u2(a0, a1, a2, a3, g_gh[(size_t)s * 32 + lane]);
        e++; cnt--;
    }

    float4 bb = *(const float4*)(b + lane * 4);
    float4 o;
    o.x = fmaxf(fmaf(a0, dinv, bb.x), 0.0f);
    o.y = fmaxf(fmaf(a1, dinv, bb.y), 0.0f);
    o.z = fmaxf(fmaf(a2, dinv, bb.z), 0.0f);
    o.w = fmaxf(fmaf(a3, dinv, bb.w), 0.0f);
    *(float4*)(out + (size_t)w * D + lane * 4) = o;
}

// ---------------- launch ----------------
extern "C" void kernel_launch(void* const* d_in, const int* in_sizes, int n_in,
                              void* d_out, int out_size)
{
    const float* x  = (const float*)d_in[0];
    const void*  ei = d_in[1];                 // [2, E], int64 OR int32 (detected)
    const float* W  = (const float*)d_in[2];
    const float* b  = (const float*)d_in[3];
    float* out = (float*)d_out;

    const int N = in_sizes[0] / D;
    const int E = in_sizes[1] / 2;
    const int NB = (N + SCAN_BLK - 1) / SCAN_BLK;

    zero_deg_kernel<<<(N + 255) / 256, 256>>>(N);
    deg_kernel<<<(E + 255) / 256, 256>>>(ei, E);
    scan1_kernel<<<NB, SCAN_BLK>>>(N);
    scan2_kernel<<<1, 128>>>(NB);
    scan3_kernel<<<NB, SCAN_BLK>>>(N);
    csr_kernel<<<(E + 255) / 256, 256>>>(ei, E);
    gemm_scale_kernel<<<(N + BM - 1) / BM, 256>>>(x, W, N);
    agg_kernel<<<(N * 32 + 255) / 256, 256>>>(b, out, N);
}

// round 12
// speedup vs baseline: 2.9210x; 1.3827x over previous
#include <cuda_runtime.h>
#include <cuda_fp16.h>
#include <cstdint>

#define N_NODES 100000
#define MAX_EDGES 1700000
#define D 128
#define SCAN_BLK 1024

// ---------------- scratch ----------------
// g stored as fp16: row = 128 halfs = 256B = 32 uint2 (each uint2 = 4 halfs)
__device__ uint2  g_gh[(size_t)N_NODES * 32];
__device__ int    g_deg[N_NODES];                    // in-degree per dst (edges only)
__device__ int    g_off[N_NODES];                    // CSR exclusive offsets
__device__ int    g_cur[N_NODES];                    // scatter cursors
__device__ int    g_csr[MAX_EDGES];                  // src index per CSR slot
__device__ int    g_bsum[128];                       // per-block scan sums
__device__ int    g_boff[128];                       // per-block scan offsets

// ---------------- helpers ----------------
__device__ __forceinline__ int block_detect_is64(const int* ei32) {
    int nz = 0;
    if (threadIdx.x < 64) nz = (ei32[2 * threadIdx.x + 1] != 0);
    return !__syncthreads_or(nz);
}

__device__ __forceinline__ void mma16816(float* c,
    unsigned a0, unsigned a1, unsigned a2, unsigned a3,
    unsigned b0, unsigned b1)
{
    asm volatile(
        "mma.sync.aligned.m16n8k16.row.col.f32.f16.f16.f32 "
        "{%0,%1,%2,%3}, {%4,%5,%6,%7}, {%8,%9}, {%0,%1,%2,%3};"
        : "+f"(c[0]), "+f"(c[1]), "+f"(c[2]), "+f"(c[3])
        : "r"(a0), "r"(a1), "r"(a2), "r"(a3), "r"(b0), "r"(b1));
}

// ---------------- kernels ----------------
__global__ void zero_deg_kernel(int n) {
    int i = blockIdx.x * blockDim.x + threadIdx.x;
    if (i < n) g_deg[i] = 0;
}

__global__ void deg_kernel(const void* __restrict__ ei, int E) {
    int is64 = block_detect_is64((const int*)ei);
    int i = blockIdx.x * blockDim.x + threadIdx.x;
    if (i >= E) return;
    int d;
    if (is64) d = (int)((const long long*)ei)[(size_t)E + i];
    else      d = ((const int*)ei)[(size_t)E + i];
    if ((unsigned)d < (unsigned)N_NODES) atomicAdd(&g_deg[d], 1);
}

// ---------------- exclusive scan of g_deg -> g_off (3 kernels, coalesced) ----
__global__ void scan1_kernel(int n) {
    __shared__ int sh[SCAN_BLK];
    int t = threadIdx.x;
    int i = blockIdx.x * SCAN_BLK + t;
    int v = (i < n) ? g_deg[i] : 0;
    sh[t] = v;
    __syncthreads();
#pragma unroll
    for (int o = 1; o < SCAN_BLK; o <<= 1) {
        int add = (t >= o) ? sh[t - o] : 0;
        __syncthreads();
        sh[t] += add;
        __syncthreads();
    }
    if (i < n) g_off[i] = sh[t] - v;          // exclusive
    if (t == SCAN_BLK - 1) g_bsum[blockIdx.x] = sh[t];
}

__global__ void scan2_kernel(int nb) {
    __shared__ int sh[128];
    int t = threadIdx.x;
    int v = (t < nb) ? g_bsum[t] : 0;
    sh[t] = v;
    __syncthreads();
#pragma unroll
    for (int o = 1; o < 128; o <<= 1) {
        int add = (t >= o) ? sh[t - o] : 0;
        __syncthreads();
        sh[t] += add;
        __syncthreads();
    }
    if (t < nb) g_boff[t] = sh[t] - v;        // exclusive
}

__global__ void scan3_kernel(int n) {
    int i = blockIdx.x * SCAN_BLK + threadIdx.x;
    if (i < n) {
        int o = g_off[i] + g_boff[blockIdx.x];
        g_off[i] = o;
        g_cur[i] = o;
    }
}

// ---------------- scatter edges into CSR (by dst) ----------------
__global__ void csr_kernel(const void* __restrict__ ei, int E) {
    int is64 = block_detect_is64((const int*)ei);
    int i = blockIdx.x * blockDim.x + threadIdx.x;
    if (i >= E) return;
    int s, d;
    if (is64) {
        const long long* p = (const long long*)ei;
        s = (int)p[i];
        d = (int)p[(size_t)E + i];
    } else {
        const int* p = (const int*)ei;
        s = p[i];
        d = p[(size_t)E + i];
    }
    if ((unsigned)s >= (unsigned)N_NODES || (unsigned)d >= (unsigned)N_NODES) return;
    int pos = atomicAdd(&g_cur[d], 1);
    g_csr[pos] = s;
}

// ---------------- HMMA GEMM: g = fp16( dinv * (x @ W^T) ) ----------------
// x rounded to fp16; W split hi+lo fp16 (2 MMAs, same fp32 accumulator) so the
// only rounding vs fp32 is x's single fp16 quantization (~2.4e-4 rms).
#define GBM 128
#define GKT 32
#define ST 40   // smem row stride in halfs (bank-permuting)
__global__ __launch_bounds__(256) void gemm_mma_kernel(
    const float* __restrict__ x, const float* __restrict__ W, int N)
{
    __shared__ __half xs[GBM][ST];   // x fp16 [m][k]
    __shared__ __half wh[D][ST];     // W hi   [n][k]
    __shared__ __half wl[D][ST];     // W lo   [n][k]

    const int tid = threadIdx.x;
    const int warpId = tid >> 5;
    const int lane = tid & 31;
    const int rowBase = blockIdx.x * GBM;
    const int warpRow = warpId * 16;
    const int qr = lane >> 2;        // 0..7
    const int qc = (lane & 3) * 2;   // 0,2,4,6

    float c[16][4];
#pragma unroll
    for (int t = 0; t < 16; t++)
#pragma unroll
        for (int j = 0; j < 4; j++) c[t][j] = 0.0f;

    for (int kt = 0; kt < D; kt += GKT) {
        // x tile -> fp16
#pragma unroll
        for (int it = 0; it < 4; it++) {
            int i = tid + it * 256;           // 0..1023 float4 slots
            int m = i >> 3;
            int kq = i & 7;
            float4 v = make_float4(0.f, 0.f, 0.f, 0.f);
            int row = rowBase + m;
            if (row < N)
                v = *(const float4*)(x + (size_t)row * D + kt + kq * 4);
            __half2 p0 = __floats2half2_rn(v.x, v.y);
            __half2 p1 = __floats2half2_rn(v.z, v.w);
            *(__half2*)&xs[m][kq * 4]     = p0;
            *(__half2*)&xs[m][kq * 4 + 2] = p1;
        }
        // W tile -> hi/lo fp16
#pragma unroll
        for (int it = 0; it < 4; it++) {
            int i = tid + it * 256;
            int n = i >> 3;
            int kq = i & 7;
            float4 v = *(const float4*)(W + (size_t)n * D + kt + kq * 4);
            __half hx = __float2half_rn(v.x);
            __half hy = __float2half_rn(v.y);
            __half hz = __float2half_rn(v.z);
            __half hw = __float2half_rn(v.w);
            __half lx = __float2half_rn(v.x - __half2float(hx));
            __half ly = __float2half_rn(v.y - __half2float(hy));
            __half lz = __float2half_rn(v.z - __half2float(hz));
            __half lw = __float2half_rn(v.w - __half2float(hw));
            *(__half2*)&wh[n][kq * 4]     = __halves2half2(hx, hy);
            *(__half2*)&wh[n][kq * 4 + 2] = __halves2half2(hz, hw);
            *(__half2*)&wl[n][kq * 4]     = __halves2half2(lx, ly);
            *(__half2*)&wl[n][kq * 4 + 2] = __halves2half2(lz, lw);
        }
        __syncthreads();

#pragma unroll
        for (int k0 = 0; k0 < GKT; k0 += 16) {
            int ar = warpRow + qr;
            int ac = k0 + qc;
            unsigned a0 = *(const unsigned*)&xs[ar][ac];
            unsigned a1 = *(const unsigned*)&xs[ar + 8][ac];
            unsigned a2 = *(const unsigned*)&xs[ar][ac + 8];
            unsigned a3 = *(const unsigned*)&xs[ar + 8][ac + 8];
#pragma unroll
            for (int t = 0; t < 16; t++) {
                int bn = t * 8 + qr;
                unsigned bh0 = *(const unsigned*)&wh[bn][ac];
                unsigned bh1 = *(const unsigned*)&wh[bn][ac + 8];
                unsigned bl0 = *(const unsigned*)&wl[bn][ac];
                unsigned bl1 = *(const unsigned*)&wl[bn][ac + 8];
                mma16816(c[t], a0, a1, a2, a3, bh0, bh1);
                mma16816(c[t], a0, a1, a2, a3, bl0, bl1);
            }
        }
        __syncthreads();
    }

    // epilogue: scale by dinv, convert to fp16 pairs, store
    int r0 = rowBase + warpRow + qr;
    int r1 = r0 + 8;
    float d0 = (r0 < N) ? rsqrtf((float)g_deg[r0] + 1.0f) : 0.0f;
    float d1 = (r1 < N) ? rsqrtf((float)g_deg[r1] + 1.0f) : 0.0f;
    unsigned* gout = (unsigned*)g_gh;          // 64 half2 per row
#pragma unroll
    for (int t = 0; t < 16; t++) {
        int colp = t * 4 + (lane & 3);         // half2 index within row
        if (r0 < N) {
            __half2 h = __floats2half2_rn(c[t][0] * d0, c[t][1] * d0);
            gout[(size_t)r0 * 64 + colp] = *(unsigned*)&h;
        }
        if (r1 < N) {
            __half2 h = __floats2half2_rn(c[t][2] * d1, c[t][3] * d1);
            gout[(size_t)r1 * 64 + colp] = *(unsigned*)&h;
        }
    }
}

// ---------------- aggregate + epilogue: warp per node, MLP=8, fp16 gather ----
__device__ __forceinline__ void acc_u2(float& a0, float& a1, float& a2, float& a3,
                                       uint2 u) {
    float2 p = __half22float2(*(__half2*)&u.x);
    float2 q = __half22float2(*(__half2*)&u.y);
    a0 += p.x; a1 += p.y; a2 += q.x; a3 += q.y;
}

__global__ __launch_bounds__(256) void agg_kernel(
    const float* __restrict__ b, float* __restrict__ out, int N)
{
    int w = (blockIdx.x * blockDim.x + threadIdx.x) >> 5;
    int lane = threadIdx.x & 31;
    if (w >= N) return;

    int deg = g_deg[w];
    int e = g_off[w];
    float dinv = rsqrtf((float)deg + 1.0f);

    float a0 = 0.f, a1 = 0.f, a2 = 0.f, a3 = 0.f;
    acc_u2(a0, a1, a2, a3, g_gh[(size_t)w * 32 + lane]);   // self loop

    int cnt = deg;
    while (cnt >= 8) {
        int s[8];
#pragma unroll
        for (int u = 0; u < 8; u++) s[u] = __ldg(&g_csr[e + u]);
        uint2 v[8];
#pragma unroll
        for (int u = 0; u < 8; u++) v[u] = g_gh[(size_t)s[u] * 32 + lane];
#pragma unroll
        for (int u = 0; u < 8; u++) acc_u2(a0, a1, a2, a3, v[u]);
        e += 8; cnt -= 8;
    }
    if (cnt >= 4) {
        int s0 = __ldg(&g_csr[e + 0]);
        int s1 = __ldg(&g_csr[e + 1]);
        int s2 = __ldg(&g_csr[e + 2]);
        int s3 = __ldg(&g_csr[e + 3]);
        uint2 v0 = g_gh[(size_t)s0 * 32 + lane];
        uint2 v1 = g_gh[(size_t)s1 * 32 + lane];
        uint2 v2 = g_gh[(size_t)s2 * 32 + lane];
        uint2 v3 = g_gh[(size_t)s3 * 32 + lane];
        acc_u2(a0, a1, a2, a3, v0);
        acc_u2(a0, a1, a2, a3, v1);
        acc_u2(a0, a1, a2, a3, v2);
        acc_u2(a0, a1, a2, a3, v3);
        e += 4; cnt -= 4;
    }
    while (cnt > 0) {
        int s = __ldg(&g_csr[e]);
        acc_u2(a0, a1, a2, a3, g_gh[(size_t)s * 32 + lane]);
        e++; cnt--;
    }

    float4 bb = *(const float4*)(b + lane * 4);
    float4 o;
    o.x = fmaxf(fmaf(a0, dinv, bb.x), 0.0f);
    o.y = fmaxf(fmaf(a1, dinv, bb.y), 0.0f);
    o.z = fmaxf(fmaf(a2, dinv, bb.z), 0.0f);
    o.w = fmaxf(fmaf(a3, dinv, bb.w), 0.0f);
    *(float4*)(out + (size_t)w * D + lane * 4) = o;
}

// ---------------- launch ----------------
extern "C" void kernel_launch(void* const* d_in, const int* in_sizes, int n_in,
                              void* d_out, int out_size)
{
    const float* x  = (const float*)d_in[0];
    const void*  ei = d_in[1];                 // [2, E], int64 OR int32 (detected)
    const float* W  = (const float*)d_in[2];
    const float* b  = (const float*)d_in[3];
    float* out = (float*)d_out;

    const int N = in_sizes[0] / D;
    const int E = in_sizes[1] / 2;
    const int NB = (N + SCAN_BLK - 1) / SCAN_BLK;

    zero_deg_kernel<<<(N + 255) / 256, 256>>>(N);
    deg_kernel<<<(E + 255) / 256, 256>>>(ei, E);
    scan1_kernel<<<NB, SCAN_BLK>>>(N);
    scan2_kernel<<<1, 128>>>(NB);
    scan3_kernel<<<NB, SCAN_BLK>>>(N);
    csr_kernel<<<(E + 255) / 256, 256>>>(ei, E);
    gemm_mma_kernel<<<(N + GBM - 1) / GBM, 256>>>(x, W, N);
    agg_kernel<<<(N * 32 + 255) / 256, 256>>>(b, out, N);
}